// round 15
// baseline (speedup 1.0000x reference)
#include <cuda_runtime.h>
#include <cuda_fp16.h>
#include <cstdint>

// Problem dims (fixed per reference)
#define DIM_M 512
#define DIM_K 4096
#define DIM_N 11008

#define CTA_M 128
#define CTA_N 128
#define KSTEP 64                 // halves / codes per K step
#define SPLITK 4
#define K_PER (DIM_K / SPLITK)   // 1024
#define ITERS (K_PER / KSTEP)    // 16
#define STAGES 2
#define GRID_MT (DIM_M / CTA_M)  // 4
#define GRID_NT (DIM_N / CTA_N)  // 86

// A rows padded to 144B (conflict-free ldmatrix); B-code rows 256B + 32 pad
#define ROWB 144
#define A_TILE (128 * ROWB)                  // 18432
#define B_ROWB 288
#define B_TILE (128 * B_ROWB)                // 36864
#define STAGE_BYTES (A_TILE + B_TILE)        // 55296
#define SMEM_TOTAL (STAGES * STAGE_BYTES)    // 110592 (x2 CTAs = 221184 <= 228KB)

// x converted to fp16, row-major [512][4096]
__device__ __align__(16) __half g_x16[DIM_M * DIM_K];
// split-K fp16 partials [SPLITK][512][11008]
__device__ __align__(16) __half g_partial[(size_t)SPLITK * DIM_M * DIM_N];

__device__ __forceinline__ uint32_t smem_u32(const void* p) {
    uint32_t a;
    asm("{ .reg .u64 t; cvta.to.shared.u64 t, %1; cvt.u32.u64 %0, t; }" : "=r"(a) : "l"(p));
    return a;
}

__device__ __forceinline__ void cp_async16(uint32_t dst, const void* src) {
    asm volatile("cp.async.cg.shared.global [%0], [%1], 16;" :: "r"(dst), "l"(src));
}
__device__ __forceinline__ void cp_commit() { asm volatile("cp.async.commit_group;"); }

__device__ __forceinline__ void ldsm4(uint32_t* r, uint32_t addr) {
    asm volatile("ldmatrix.sync.aligned.m8n8.x4.shared.b16 {%0,%1,%2,%3}, [%4];"
                 : "=r"(r[0]), "=r"(r[1]), "=r"(r[2]), "=r"(r[3]) : "r"(addr));
}

__device__ __forceinline__ void lds2(uint32_t& c0, uint32_t& c1, uint32_t addr) {
    asm volatile("ld.shared.v2.u32 {%0,%1}, [%2];" : "=r"(c0), "=r"(c1) : "r"(addr));
}

__device__ __forceinline__ void mma16816(float* d, const uint32_t* a, const uint32_t* b) {
    asm volatile(
        "mma.sync.aligned.m16n8k16.row.col.f32.f16.f16.f32 "
        "{%0,%1,%2,%3}, {%4,%5,%6,%7}, {%8,%9}, {%0,%1,%2,%3};"
        : "+f"(d[0]), "+f"(d[1]), "+f"(d[2]), "+f"(d[3])
        : "r"(a[0]), "r"(a[1]), "r"(a[2]), "r"(a[3]), "r"(b[0]), "r"(b[1]));
}

__device__ __forceinline__ uint32_t pack2(float a, float b) {
    __half2 h = __floats2half2_rn(a, b);
    return *reinterpret_cast<uint32_t*>(&h);
}

// ---------------- kernel 0: x fp32 -> fp16 row-major ----------------
__global__ void __launch_bounds__(256) convert_x_kernel(const float* __restrict__ x) {
    int gid = blockIdx.x * blockDim.x + threadIdx.x;
    const float4* src = reinterpret_cast<const float4*>(x) + gid * 2;
    float4 f0 = __ldg(src);
    float4 f1 = __ldg(src + 1);
    uint4 v;
    v.x = pack2(f0.x, f0.y);
    v.y = pack2(f0.z, f0.w);
    v.z = pack2(f1.x, f1.y);
    v.w = pack2(f1.z, f1.w);
    reinterpret_cast<uint4*>(g_x16)[gid] = v;
}

// ---------------- kernel 1: fused int4-dequant fp16 HMMA GEMM, split-K x4 ----------------
// B path: raw int32 codes staged in SMEM via cp.async; mma B fragments built
// just-in-time in registers (LDS.64 x2 + I2F + FFMA + pack), hidden under the
// HMMA issue ceiling.
__global__ void __launch_bounds__(256, 2) gemm_kernel(const int* __restrict__ w,
                                                      const float* __restrict__ saz) {
    extern __shared__ __align__(1024) char smem[];
    const uint32_t sb = smem_u32(smem);
    const int tid = threadIdx.x;
    const int wid = tid >> 5;
    const int lid = tid & 31;

    // decode: mtile fastest (4), then kq (4), then ntile -> 16 adjacent CTAs share a B slab
    const int mtile = blockIdx.x & 3;
    const int kq = (blockIdx.x >> 2) & 3;
    const int ntile = blockIdx.x >> 4;
    const int mbase = mtile * CTA_M;
    const int nbase = ntile * CTA_N;
    const int kbase = kq * K_PER;

    // 2x4 warp grid, warp tile 64x32 (4 m16 sub-tiles per warp)
    const int m0w = (wid & 1) * 64;
    const int n0w = (wid >> 1) * 32;

    // ---- A loader: tile 128 rows x 8 chunks(16B); 4 chunks/thread ----
    const int r0 = tid >> 3;         // 0..31
    const int c  = tid & 7;          // 0..7
    const __half* aG = g_x16 + (size_t)(mbase + r0) * DIM_K + kbase + c * 8;
    const uint32_t a_ld_off = (uint32_t)r0 * ROWB + c * 16;
    const size_t gstep32 = (size_t)32 * DIM_K;
    const uint32_t sstep32 = 32u * ROWB;

    // ---- B-code loader: tile 128 rows x 16 chunks(16B = 4 int32); 8 chunks/thread ----
    // thread covers rows (tid>>4) + j*16, fixed 16B-chunk (tid&15)
    const int* wptr = w + (size_t)(nbase + (tid >> 4)) * DIM_K + kbase + (tid & 15) * 4;
    const uint32_t b_ld_off = (uint32_t)(tid >> 4) * B_ROWB + (tid & 15) * 16;

    // ---- fragment address bases ----
    const uint32_t a_lane_off = (uint32_t)(m0w + (lid & 15)) * ROWB + ((lid >> 4) << 4);
    // B fragment codes: row n = n0w + n8*8 + (lid>>2), k = kc*16 + (lid&3)*2 (+8)
    const uint32_t b_frag_off = (uint32_t)(n0w + (lid >> 2)) * B_ROWB + (lid & 3) * 8;

    // scales: per-row float2 (s, z)
    const float2* szG = reinterpret_cast<const float2*>(saz) + (nbase + n0w + (lid >> 2));

    float d[4][4][4];
    #pragma unroll
    for (int i = 0; i < 4; ++i)
        #pragma unroll
        for (int j = 0; j < 4; ++j)
            #pragma unroll
            for (int k = 0; k < 4; ++k) d[i][j][k] = 0.f;

    #define ISSUE_STAGE(ks, buf) do {                                     \
        const uint32_t stA = sb + (buf) * STAGE_BYTES + a_ld_off;         \
        const __half* sa = aG + (ks) * KSTEP;                             \
        cp_async16(stA,               sa);                                \
        cp_async16(stA + sstep32,     sa + gstep32);                      \
        cp_async16(stA + 2 * sstep32, sa + 2 * gstep32);                  \
        cp_async16(stA + 3 * sstep32, sa + 3 * gstep32);                  \
        const uint32_t stB = sb + (buf) * STAGE_BYTES + A_TILE + b_ld_off;\
        const int* ws = wptr + (ks) * KSTEP;                              \
        _Pragma("unroll")                                                 \
        for (int j = 0; j < 8; ++j)                                       \
            cp_async16(stB + j * (16 * B_ROWB), ws + (size_t)j * 16 * DIM_K); \
    } while (0)

    // ---- prologue: stage 0 in flight ----
    ISSUE_STAGE(0, 0);
    cp_commit();

    for (int ks = 0; ks < ITERS; ++ks) {
        asm volatile("cp.async.wait_group 0;");
        __syncthreads();

        // prefetch next stage into the buffer consumed at ks-1 (certified free by sync)
        if (ks + 1 < ITERS) ISSUE_STAGE(ks + 1, (ks + 1) & 1);
        cp_commit();

        // per-iter scales: group = kq*8 + ks/2 (KSTEP=64, groupsize=128)
        const int g = kq * 8 + (ks >> 1);
        float s4[4], zs4[4];
        #pragma unroll
        for (int n8 = 0; n8 < 4; ++n8) {
            float2 sz = __ldg(szG + (size_t)g * DIM_N + n8 * 8);
            s4[n8] = sz.x;
            zs4[n8] = sz.y - 8.0f * sz.x;
        }

        const int buf = ks & 1;
        const uint32_t aBase = sb + buf * STAGE_BYTES + a_lane_off;
        const uint32_t bfb = sb + buf * STAGE_BYTES + A_TILE + b_frag_off;
        #pragma unroll
        for (int kc = 0; kc < 4; ++kc) {
            uint32_t a[4][4];
            #pragma unroll
            for (int mt = 0; mt < 4; ++mt)
                ldsm4(a[mt], aBase + (uint32_t)mt * (16 * ROWB) + kc * 32);
            #pragma unroll
            for (int n8 = 0; n8 < 4; ++n8) {
                const uint32_t addr = bfb + (uint32_t)n8 * (8 * B_ROWB) + kc * 64;
                uint32_t c0, c1, c2, c3;
                lds2(c0, c1, addr);
                lds2(c2, c3, addr + 32);
                const float s = s4[n8], zs = zs4[n8];
                uint32_t bb[2];
                bb[0] = pack2(__int2float_rn((int)c0) * s + zs,
                              __int2float_rn((int)c1) * s + zs);
                bb[1] = pack2(__int2float_rn((int)c2) * s + zs,
                              __int2float_rn((int)c3) * s + zs);
                #pragma unroll
                for (int mt = 0; mt < 4; ++mt)
                    mma16816(d[mt][n8], a[mt], bb);
            }
        }
    }

    // ---- epilogue: registers -> fp16 split-K partial ----
    __half* pout = g_partial + (size_t)kq * DIM_M * DIM_N;
    const int gg = lid >> 2;
    const int tc = (lid & 3) * 2;
    #pragma unroll
    for (int mt = 0; mt < 4; ++mt) {
        const int row0 = mbase + m0w + mt * 16 + gg;
        #pragma unroll
        for (int n8 = 0; n8 < 4; ++n8) {
            const int col = nbase + n0w + n8 * 8 + tc;
            *reinterpret_cast<uint32_t*>(pout + (size_t)row0 * DIM_N + col) =
                pack2(d[mt][n8][0], d[mt][n8][1]);
            *reinterpret_cast<uint32_t*>(pout + (size_t)(row0 + 8) * DIM_N + col) =
                pack2(d[mt][n8][2], d[mt][n8][3]);
        }
    }
}

// ---------------- kernel 2: sum fp16 split-K partials -> fp32 out ----------------
__global__ void __launch_bounds__(256) reduce_kernel(float* __restrict__ out) {
    const size_t gid = (size_t)blockIdx.x * blockDim.x + threadIdx.x;  // per 8 halves
    const uint4* p = reinterpret_cast<const uint4*>(g_partial);
    const size_t q = (size_t)DIM_M * DIM_N / 8;
    uint4 v[SPLITK];
    v[0] = __ldcs(p + gid);
    v[1] = __ldcs(p + gid + q);
    v[2] = __ldcs(p + gid + 2 * q);
    v[3] = __ldcs(p + gid + 3 * q);
    float acc[8];
    #pragma unroll
    for (int i = 0; i < 8; ++i) acc[i] = 0.f;
    #pragma unroll
    for (int s = 0; s < SPLITK; ++s) {
        const uint32_t* u = reinterpret_cast<const uint32_t*>(&v[s]);
        #pragma unroll
        for (int j = 0; j < 4; ++j) {
            __half2 h = *reinterpret_cast<const __half2*>(&u[j]);
            float2 f = __half22float2(h);
            acc[2 * j] += f.x;
            acc[2 * j + 1] += f.y;
        }
    }
    float4 r0, r1;
    r0.x = acc[0]; r0.y = acc[1]; r0.z = acc[2]; r0.w = acc[3];
    r1.x = acc[4]; r1.y = acc[5]; r1.z = acc[6]; r1.w = acc[7];
    reinterpret_cast<float4*>(out)[2 * gid] = r0;
    reinterpret_cast<float4*>(out)[2 * gid + 1] = r1;
}

extern "C" void kernel_launch(void* const* d_in, const int* in_sizes, int n_in,
                              void* d_out, int out_size) {
    const float* x   = (const float*)d_in[0];
    const int*   w   = (const int*)d_in[1];
    const float* saz = (const float*)d_in[2];
    float* out = (float*)d_out;

    cudaFuncSetAttribute(gemm_kernel, cudaFuncAttributeMaxDynamicSharedMemorySize, SMEM_TOTAL);

    convert_x_kernel<<<(DIM_M * DIM_K / 8) / 256, 256>>>(x);
    gemm_kernel<<<GRID_MT * GRID_NT * SPLITK, 256, SMEM_TOTAL>>>(w, saz);
    reduce_kernel<<<(DIM_M * DIM_N / 8) / 256, 256>>>(out);
}